// round 15
// baseline (speedup 1.0000x reference)
#include <cuda_runtime.h>
#include <cuda_fp16.h>
#include <cstdint>
#include <cstddef>

#define B_ 4
#define S_ 2048
#define H_ 256
#define NHEAD_ 4
#define DH_ 64
#define FFN_ 1024
#define M_ (B_ * S_)   // 8192

// weight-scratch segment offsets (elements)
#define O_WIN   0
#define O_WOUT  65536
#define O_QKV   131072
#define O_OUTW  720896
#define O_FF1   917504
#define O_FF2   1703936
#define WTOT    2490368
#define XTOT    2097152
#define TOT     (WTOT + XTOT)

// ---------------- scratch (no allocation allowed) ----------------
__device__ float  g_h  [M_ * H_];          // fp32 residual stream
__device__ __half g_z  [M_ * H_];          // LN output (half)
__device__ __half g_qkv[M_ * 3 * H_];
__device__ __half g_att[M_ * H_];
__device__ __half g_ffn[M_ * FFN_];
__device__ __half g_wc [WTOT];             // half weights
__device__ __half g_xr [XTOT];             // half x

__device__ __forceinline__ void cp_async16(uint32_t smem, const void* gmem) {
    asm volatile("cp.async.cg.shared.global [%0], [%1], 16;\n" :: "r"(smem), "l"(gmem));
}
__device__ __forceinline__ void cp_commit() {
    asm volatile("cp.async.commit_group;\n");
}
template<int N>
__device__ __forceinline__ void cp_wait() {
    asm volatile("cp.async.wait_group %0;\n" :: "n"(N));
}

#define MMA_F16(acc, a, b0, b1)                                               \
    asm volatile(                                                             \
        "mma.sync.aligned.m16n8k16.row.col.f32.f16.f16.f32 "                  \
        "{%0,%1,%2,%3}, {%4,%5,%6,%7}, {%8,%9}, {%0,%1,%2,%3};\n"             \
        : "+f"(acc[0]), "+f"(acc[1]), "+f"(acc[2]), "+f"(acc[3])              \
        : "r"(a[0]), "r"(a[1]), "r"(a[2]), "r"(a[3]), "r"(b0), "r"(b1))

__device__ __forceinline__ uint32_t h2u(__half2 h) { return *(uint32_t*)&h; }
__device__ __forceinline__ uint32_t pack2(float lo, float hi) {
    __half2 h = __halves2half2(__float2half_rn(lo), __float2half_rn(hi));
    return h2u(h);
}

// ---------------- prep: round weights + x to fp16 once per launch ----------------
__global__ void __launch_bounds__(256)
prep_cvt(const float* __restrict__ w_in, const float* __restrict__ w_out,
         const float* __restrict__ qkv_w, const float* __restrict__ out_w,
         const float* __restrict__ ff1_w, const float* __restrict__ ff2_w,
         const float* __restrict__ x, __half* __restrict__ wc, __half* __restrict__ xr)
{
    int i = (blockIdx.x * 256 + threadIdx.x) * 4;
    if (i >= TOT) return;
    const float* s;
    __half* d;
    if (i < O_QKV) {
        s = (i < O_WOUT) ? (w_in + i) : (w_out + (i - O_WOUT));
        d = wc + i;
    } else if (i < O_OUTW) { s = qkv_w + (i - O_QKV);  d = wc + i; }
    else if (i < O_FF1)    { s = out_w + (i - O_OUTW); d = wc + i; }
    else if (i < O_FF2)    { s = ff1_w + (i - O_FF1);  d = wc + i; }
    else if (i < WTOT)     { s = ff2_w + (i - O_FF2);  d = wc + i; }
    else                   { s = x + (i - WTOT);       d = xr + (i - WTOT); }
    float4 v = *(const float4*)s;
    uint2 o;
    o.x = pack2(v.x, v.y);
    o.y = pack2(v.z, v.w);
    *(uint2*)d = o;
}

#define ASTR 40   // halves per smem row (k-tile 32 + pad 8)

// ---------------- FP16 GEMM, TMx128 tile (qkv / ff1 / final) ----------------
// MODE 0: +bias, 1: +bias+relu. OUTH: half out else fp32.
template<int MODE, bool OUTH, int TM>
__global__ void __launch_bounds__(256)
gemm_h(const __half* __restrict__ A, const __half* __restrict__ W,
       const float* __restrict__ bias, const float* __restrict__ res,
       void* __restrict__ Cv, int M, int N, int K)
{
    constexpr int RM = TM / 32;
    constexpr int WN = 128 / (8 / RM);
    constexpr int NT = WN / 8;
    extern __shared__ __half hs[];
    __half (*As)[TM][ASTR]  = (__half (*)[TM][ASTR])hs;
    __half (*Bs)[128][ASTR] = (__half (*)[128][ASTR])(hs + 2 * TM * ASTR);

    const int tid = threadIdx.x;
    const int lane = tid & 31;
    const int wid = tid >> 5;
    const int bm = blockIdx.y * TM;
    const int bn = blockIdx.x * 128;
    const int warp_m = (wid % RM) * 32;
    const int warp_n = (wid / RM) * WN;
    const int gid = lane >> 2;
    const int tig = lane & 3;

    float acc[2][NT][4];
#pragma unroll
    for (int i = 0; i < 2; i++)
#pragma unroll
        for (int j = 0; j < NT; j++)
#pragma unroll
            for (int c = 0; c < 4; c++) acc[i][j][c] = 0.f;

    const int nk = K >> 5;

    auto stage = [&](int buf, int k0) {
#pragma unroll
        for (int p = 0; p < TM / 64; p++) {
            int e = tid + p * 256;
            int r = e >> 2, c = e & 3;
            uint32_t s = (uint32_t)__cvta_generic_to_shared(&As[buf][r][c * 8]);
            cp_async16(s, A + (size_t)(bm + r) * K + k0 + c * 8);
        }
#pragma unroll
        for (int p = 0; p < 2; p++) {
            int e = tid + p * 256;
            int r = e >> 2, c = e & 3;
            uint32_t s = (uint32_t)__cvta_generic_to_shared(&Bs[buf][r][c * 8]);
            cp_async16(s, W + (size_t)(bn + r) * K + k0 + c * 8);
        }
        cp_commit();
    };

    stage(0, 0);

    for (int it = 0; it < nk; it++) {
        if (it + 1 < nk) {
            stage((it + 1) & 1, (it + 1) * 32);
            cp_wait<1>();
        } else {
            cp_wait<0>();
        }
        __syncthreads();

        const __half (*Asb)[ASTR] = As[it & 1];
        const __half (*Bsb)[ASTR] = Bs[it & 1];

#pragma unroll
        for (int ks = 0; ks < 32; ks += 16) {
            uint32_t a[2][4];
#pragma unroll
            for (int mt = 0; mt < 2; mt++) {
                int m0 = warp_m + mt * 16 + gid;
                a[mt][0] = *(const uint32_t*)&Asb[m0][ks + 2 * tig];
                a[mt][1] = *(const uint32_t*)&Asb[m0 + 8][ks + 2 * tig];
                a[mt][2] = *(const uint32_t*)&Asb[m0][ks + 2 * tig + 8];
                a[mt][3] = *(const uint32_t*)&Asb[m0 + 8][ks + 2 * tig + 8];
            }
#pragma unroll
            for (int nt = 0; nt < NT; nt++) {
                int n0 = warp_n + nt * 8 + gid;
                uint32_t b0 = *(const uint32_t*)&Bsb[n0][ks + 2 * tig];
                uint32_t b1 = *(const uint32_t*)&Bsb[n0][ks + 2 * tig + 8];
#pragma unroll
                for (int mt = 0; mt < 2; mt++)
                    MMA_F16(acc[mt][nt], a[mt], b0, b1);
            }
        }
        __syncthreads();
    }

#pragma unroll
    for (int mt = 0; mt < 2; mt++) {
#pragma unroll
        for (int half_ = 0; half_ < 2; half_++) {
            int m = bm + warp_m + mt * 16 + gid + half_ * 8;
#pragma unroll
            for (int nt = 0; nt < NT; nt++) {
                int n = bn + warp_n + nt * 8 + 2 * tig;
                float v0 = acc[mt][nt][half_ * 2 + 0];
                float v1 = acc[mt][nt][half_ * 2 + 1];
                v0 += bias[n];
                v1 += bias[n + 1];
                if (MODE == 1) { v0 = fmaxf(v0, 0.f); v1 = fmaxf(v1, 0.f); }
                if (OUTH) {
                    *(uint32_t*)((__half*)Cv + (size_t)m * N + n) = pack2(v0, v1);
                } else {
                    *(float2*)((float*)Cv + (size_t)m * N + n) = make_float2(v0, v1);
                }
            }
        }
    }
}

// ---------------- FP16 GEMM 32x256 tile + fused LayerNorm epilogue ----------------
// MODE 3: v = 16*acc + PE (embed). MODE 2: v = acc + bias + res (residual).
// Writes h (fp32) and z = LN(v) (half). 256 CTAs (M/32) — full-chip coverage.
#define CSTR 264   // fp32 row-buffer stride (floats)
#define GLN_SMEM_BYTES ((2 * 32 * ASTR + 2 * 256 * ASTR) * 2)   // 46080 > Cbuf 33792

template<int MODE>
__global__ void __launch_bounds__(256)
gemm_ln(const __half* __restrict__ A, const __half* __restrict__ W,
        const float* __restrict__ bias, const float* __restrict__ res,
        float* __restrict__ Hout, __half* __restrict__ Zout,
        const float* __restrict__ lng, const float* __restrict__ lnb, int K)
{
    constexpr int N = 256;
    extern __shared__ __half hs[];
    __half (*As)[32][ASTR]  = (__half (*)[32][ASTR])hs;
    __half (*Bs)[256][ASTR] = (__half (*)[256][ASTR])(hs + 2 * 32 * ASTR);
    float* Cbuf = (float*)hs;  // epilogue union (pipeline dead by then)

    const int tid = threadIdx.x;
    const int lane = tid & 31;
    const int wid = tid >> 5;
    const int bm = blockIdx.x * 32;
    const int warp_n = wid * 32;           // 8 warps x 32 cols = 256
    const int gid = lane >> 2;
    const int tig = lane & 3;

    float acc[2][4][4];
#pragma unroll
    for (int i = 0; i < 2; i++)
#pragma unroll
        for (int j = 0; j < 4; j++)
#pragma unroll
            for (int c = 0; c < 4; c++) acc[i][j][c] = 0.f;

    const int nk = K >> 5;

    auto stage = [&](int buf, int k0) {
        if (tid < 128) {                     // 32 rows x 4 chunks = 128
            int r = tid >> 2, c = tid & 3;
            uint32_t s = (uint32_t)__cvta_generic_to_shared(&As[buf][r][c * 8]);
            cp_async16(s, A + (size_t)(bm + r) * K + k0 + c * 8);
        }
#pragma unroll
        for (int p = 0; p < 4; p++) {        // 256 rows x 4 chunks = 1024
            int e = tid + p * 256;
            int r = e >> 2, c = e & 3;
            uint32_t s = (uint32_t)__cvta_generic_to_shared(&Bs[buf][r][c * 8]);
            cp_async16(s, W + (size_t)r * K + k0 + c * 8);
        }
        cp_commit();
    };

    stage(0, 0);

    for (int it = 0; it < nk; it++) {
        if (it + 1 < nk) {
            stage((it + 1) & 1, (it + 1) * 32);
            cp_wait<1>();
        } else {
            cp_wait<0>();
        }
        __syncthreads();

        const __half (*Asb)[ASTR] = As[it & 1];
        const __half (*Bsb)[ASTR] = Bs[it & 1];

#pragma unroll
        for (int ks = 0; ks < 32; ks += 16) {
            uint32_t a[2][4];
#pragma unroll
            for (int mt = 0; mt < 2; mt++) {
                int m0 = mt * 16 + gid;
                a[mt][0] = *(const uint32_t*)&Asb[m0][ks + 2 * tig];
                a[mt][1] = *(const uint32_t*)&Asb[m0 + 8][ks + 2 * tig];
                a[mt][2] = *(const uint32_t*)&Asb[m0][ks + 2 * tig + 8];
                a[mt][3] = *(const uint32_t*)&Asb[m0 + 8][ks + 2 * tig + 8];
            }
#pragma unroll
            for (int nt = 0; nt < 4; nt++) {
                int n0 = warp_n + nt * 8 + gid;
                uint32_t b0 = *(const uint32_t*)&Bsb[n0][ks + 2 * tig];
                uint32_t b1 = *(const uint32_t*)&Bsb[n0][ks + 2 * tig + 8];
#pragma unroll
                for (int mt = 0; mt < 2; mt++)
                    MMA_F16(acc[mt][nt], a[mt], b0, b1);
            }
        }
        __syncthreads();
    }

    // ---- epilogue: compute v, write h (fp32) + stash rows in smem ----
#pragma unroll
    for (int mt = 0; mt < 2; mt++) {
#pragma unroll
        for (int half_ = 0; half_ < 2; half_++) {
            int rl = mt * 16 + gid + half_ * 8;
            int m = bm + rl;
#pragma unroll
            for (int nt = 0; nt < 4; nt++) {
                int n = warp_n + nt * 8 + 2 * tig;
                float v0 = acc[mt][nt][half_ * 2 + 0];
                float v1 = acc[mt][nt][half_ * 2 + 1];
                if (MODE == 3) {
                    int s = m & (S_ - 1);
                    float f0 = expf((float)(n & ~1) * (-9.210340371976184f / 256.0f));
                    float ang = (float)s * f0;
                    v0 = 16.f * v0 + sinf(ang);
                    v1 = 16.f * v1 + cosf(ang);
                } else {
                    v0 += bias[n];
                    v1 += bias[n + 1];
                    const float* rp = res + (size_t)m * N + n;
                    v0 += rp[0];
                    v1 += rp[1];
                }
                *(float2*)&Cbuf[rl * CSTR + n] = make_float2(v0, v1);
                *(float2*)(Hout + (size_t)m * N + n) = make_float2(v0, v1);
            }
        }
    }
    __syncthreads();

    // ---- LayerNorm: warp per row (4 rows/warp), identical math to ln_kernel ----
#pragma unroll
    for (int i = 0; i < 4; i++) {
        int rl = wid * 4 + i;
        int m = bm + rl;
        const float4* xr = (const float4*)&Cbuf[rl * CSTR];
        float4 v0 = xr[lane], v1 = xr[lane + 32];
        float s = v0.x + v0.y + v0.z + v0.w + v1.x + v1.y + v1.z + v1.w;
#pragma unroll
        for (int o = 16; o; o >>= 1) s += __shfl_xor_sync(~0u, s, o);
        float mu = s * (1.f / 256.f);
        float sq = 0.f;
        sq += (v0.x - mu) * (v0.x - mu) + (v0.y - mu) * (v0.y - mu)
            + (v0.z - mu) * (v0.z - mu) + (v0.w - mu) * (v0.w - mu);
        sq += (v1.x - mu) * (v1.x - mu) + (v1.y - mu) * (v1.y - mu)
            + (v1.z - mu) * (v1.z - mu) + (v1.w - mu) * (v1.w - mu);
#pragma unroll
        for (int o = 16; o; o >>= 1) sq += __shfl_xor_sync(~0u, sq, o);
        float rs = rsqrtf(sq * (1.f / 256.f) + 1e-5f);
        float4 g0 = ((const float4*)lng)[lane], g1 = ((const float4*)lng)[lane + 32];
        float4 b0 = ((const float4*)lnb)[lane], b1 = ((const float4*)lnb)[lane + 32];
        uint2 o0, o1;
        o0.x = pack2((v0.x - mu) * rs * g0.x + b0.x, (v0.y - mu) * rs * g0.y + b0.y);
        o0.y = pack2((v0.z - mu) * rs * g0.z + b0.z, (v0.w - mu) * rs * g0.w + b0.w);
        o1.x = pack2((v1.x - mu) * rs * g1.x + b1.x, (v1.y - mu) * rs * g1.y + b1.y);
        o1.y = pack2((v1.z - mu) * rs * g1.z + b1.z, (v1.w - mu) * rs * g1.w + b1.w);
        uint2* yr = (uint2*)(Zout + (size_t)m * 256);
        yr[lane] = o0;
        yr[lane + 32] = o1;
    }
}

// ---------------- FP16 tensor-core banded attention (unchanged) ----------------
#define BQ 64
#define QSTRH 72
#define KSTRH 72
#define PSTRF 132
#define VSTRH 136
#define PHSTR 136
#define PS_F   (64 * PSTRF)
#define ATT_SMEM_BYTES (PS_F * 4 + 128 * KSTRH * 2 + 64 * VSTRH * 2 + 64 * PHSTR * 2 + 64 * 4)

__global__ void __launch_bounds__(256)
attn_h(const __half* __restrict__ qkv, __half* __restrict__ out)
{
    extern __shared__ float asmem[];
    float*  Ps   = asmem;
    __half* Qs   = (__half*)asmem;
    __half* Ks   = (__half*)(asmem + PS_F);
    __half* Vt   = Ks + 128 * KSTRH;
    __half* Ph   = Vt + 64 * VSTRH;
    float*  Rinv = (float*)(Ph + 64 * PHSTR);

    const int q0 = blockIdx.x * BQ;
    const int h = blockIdx.y;
    const int bb = blockIdx.z;
    const int tid = threadIdx.x;
    const int lane = tid & 31;
    const int wid = tid >> 5;
    const int gid = lane >> 2;
    const int tig = lane & 3;
    const __half* base = qkv + (size_t)bb * S_ * (3 * H_) + h * 64;
    const int kb = q0 - 32;

#pragma unroll
    for (int p = 0; p < 2; p++) {
        int e = tid + p * 256;
        int r = e >> 3, c = e & 7;
        *(uint4*)&Qs[r * QSTRH + c * 8] =
            *(const uint4*)(base + (size_t)(q0 + r) * (3 * H_) + c * 8);
    }
#pragma unroll
    for (int p = 0; p < 4; p++) {
        int e = tid + p * 256;
        int r = e >> 3, c = e & 7;
        int j = kb + r;
        uint4 kk = make_uint4(0, 0, 0, 0);
        if (j >= 0 && j < S_)
            kk = *(const uint4*)(base + (size_t)j * (3 * H_) + H_ + c * 8);
        *(uint4*)&Ks[r * KSTRH + c * 8] = kk;
    }
#pragma unroll
    for (int p = 0; p < 16; p++) {
        int e = tid + p * 256;
        int r = e >> 5;
        int d2 = e & 31;
        int j = kb + r;
        __half2 vv = __halves2half2(__ushort_as_half(0), __ushort_as_half(0));
        if (j >= 0 && j < S_)
            vv = *(const __half2*)(base + (size_t)j * (3 * H_) + 2 * H_ + 2 * d2);
        Vt[(2 * d2) * VSTRH + r]     = __low2half(vv);
        Vt[(2 * d2 + 1) * VSTRH + r] = __high2half(vv);
    }
    __syncthreads();

    const int warp_m = (wid & 3) * 16;

    float sacc[8][4];
    {
        const int warp_n = (wid >> 2) * 64;
#pragma unroll
        for (int j = 0; j < 8; j++)
#pragma unroll
            for (int c = 0; c < 4; c++) sacc[j][c] = 0.f;

#pragma unroll
        for (int ks = 0; ks < 64; ks += 16) {
            uint32_t a[4];
            a[0] = *(const uint32_t*)&Qs[(warp_m + gid) * QSTRH + ks + 2 * tig];
            a[1] = *(const uint32_t*)&Qs[(warp_m + gid + 8) * QSTRH + ks + 2 * tig];
            a[2] = *(const uint32_t*)&Qs[(warp_m + gid) * QSTRH + ks + 2 * tig + 8];
            a[3] = *(const uint32_t*)&Qs[(warp_m + gid + 8) * QSTRH + ks + 2 * tig + 8];
#pragma unroll
            for (int nt = 0; nt < 8; nt++) {
                int n0 = warp_n + nt * 8 + gid;
                uint32_t b0 = *(const uint32_t*)&Ks[n0 * KSTRH + ks + 2 * tig];
                uint32_t b1 = *(const uint32_t*)&Ks[n0 * KSTRH + ks + 2 * tig + 8];
                MMA_F16(sacc[nt], a, b0, b1);
            }
        }
    }
    __syncthreads();

    {
        const int warp_n = (wid >> 2) * 64;
#pragma unroll
        for (int nt = 0; nt < 8; nt++) {
#pragma unroll
            for (int half_ = 0; half_ < 2; half_++) {
                int r = warp_m + gid + half_ * 8;
                int c = warp_n + nt * 8 + 2 * tig;
                *(float2*)&Ps[r * PSTRF + c] =
                    make_float2(sacc[nt][half_ * 2] * 0.125f,
                                sacc[nt][half_ * 2 + 1] * 0.125f);
            }
        }
    }
    __syncthreads();

    {
#pragma unroll
        for (int i = 0; i < 8; i++) {
            int r = wid * 8 + i;
            float4 v = *(float4*)&Ps[r * PSTRF + lane * 4];
            float pv[4] = {v.x, v.y, v.z, v.w};
            bool ok[4];
            float mx = -1e30f;
#pragma unroll
            for (int t = 0; t < 4; t++) {
                int c = lane * 4 + t;
                int j = kb + c;
                ok[t] = (c >= r) && (c <= r + 64) && (j >= 0) && (j < S_);
                if (ok[t]) mx = fmaxf(mx, pv[t]);
            }
#pragma unroll
            for (int o = 16; o; o >>= 1) mx = fmaxf(mx, __shfl_xor_sync(~0u, mx, o));
            float s = 0.f;
#pragma unroll
            for (int t = 0; t < 4; t++) {
                pv[t] = ok[t] ? __expf(pv[t] - mx) : 0.f;
                s += pv[t];
            }
#pragma unroll
            for (int o = 16; o; o >>= 1) s += __shfl_xor_sync(~0u, s, o);
            uint2 ph;
            ph.x = pack2(pv[0], pv[1]);
            ph.y = pack2(pv[2], pv[3]);
            *(uint2*)&Ph[r * PHSTR + lane * 4] = ph;
            if (lane == 0) Rinv[r] = 1.f / s;
        }
    }
    __syncthreads();

    {
        const int warp_n = (wid >> 2) * 32;
        float acc[4][4];
#pragma unroll
        for (int j = 0; j < 4; j++)
#pragma unroll
            for (int c = 0; c < 4; c++) acc[j][c] = 0.f;

#pragma unroll
        for (int k0 = 0; k0 < 128; k0 += 16) {
            uint32_t a[4];
            a[0] = *(const uint32_t*)&Ph[(warp_m + gid) * PHSTR + k0 + 2 * tig];
            a[1] = *(const uint32_t*)&Ph[(warp_m + gid + 8) * PHSTR + k0 + 2 * tig];
            a[2] = *(const uint32_t*)&Ph[(warp_m + gid) * PHSTR + k0 + 2 * tig + 8];
            a[3] = *(const uint32_t*)&Ph[(warp_m + gid + 8) * PHSTR + k0 + 2 * tig + 8];
#pragma unroll
            for (int nt = 0; nt < 4; nt++) {
                int d0 = warp_n + nt * 8 + gid;
                uint32_t b0 = *(const uint32_t*)&Vt[d0 * VSTRH + k0 + 2 * tig];
                uint32_t b1 = *(const uint32_t*)&Vt[d0 * VSTRH + k0 + 2 * tig + 8];
                MMA_F16(acc[nt], a, b0, b1);
            }
        }

#pragma unroll
        for (int nt = 0; nt < 4; nt++) {
#pragma unroll
            for (int half_ = 0; half_ < 2; half_++) {
                int r = warp_m + gid + half_ * 8;
                float sc = Rinv[r];
                int c = warp_n + nt * 8 + 2 * tig;
                *(uint32_t*)(out + (size_t)(bb * S_ + q0 + r) * H_ + h * 64 + c) =
                    pack2(acc[nt][half_ * 2] * sc, acc[nt][half_ * 2 + 1] * sc);
            }
        }
    }
}

// ---------------- host orchestration ----------------
template<int MODE, bool OUTH, int TM>
static void launch_gemm(const __half* A, const __half* W, const float* bias,
                        const float* res, void* C, int M, int N, int K)
{
    const int smem = (2 * TM * ASTR + 2 * 128 * ASTR) * 2;
    static bool attr_set = false;
    if (!attr_set) {
        cudaFuncSetAttribute(gemm_h<MODE, OUTH, TM>,
                             cudaFuncAttributeMaxDynamicSharedMemorySize, smem);
        attr_set = true;
    }
    dim3 grid(N / 128, M / TM);
    gemm_h<MODE, OUTH, TM><<<grid, 256, smem>>>(A, W, bias, res, C, M, N, K);
}

template<int MODE>
static void launch_gemm_ln(const __half* A, const __half* W, const float* bias,
                           const float* res, float* Hout, __half* Zout,
                           const float* lng, const float* lnb, int K)
{
    static bool attr_set = false;
    if (!attr_set) {
        cudaFuncSetAttribute(gemm_ln<MODE>,
                             cudaFuncAttributeMaxDynamicSharedMemorySize, GLN_SMEM_BYTES);
        attr_set = true;
    }
    gemm_ln<MODE><<<M_ / 32, 256, GLN_SMEM_BYTES>>>(A, W, bias, res, Hout, Zout,
                                                    lng, lnb, K);
}

extern "C" void kernel_launch(void* const* d_in, const int* in_sizes, int n_in,
                              void* d_out, int out_size)
{
    const float* x     = (const float*)d_in[0];
    const float* w_in  = (const float*)d_in[1];
    const float* w_out = (const float*)d_in[2];
    const float* b_out = (const float*)d_in[3];
    const float* qkv_w = (const float*)d_in[4];
    const float* qkv_b = (const float*)d_in[5];
    const float* out_w = (const float*)d_in[6];
    const float* out_b = (const float*)d_in[7];
    const float* ln1_g = (const float*)d_in[8];
    const float* ln1_b = (const float*)d_in[9];
    const float* ln2_g = (const float*)d_in[10];
    const float* ln2_b = (const float*)d_in[11];
    const float* ff1_w = (const float*)d_in[12];
    const float* ff1_b = (const float*)d_in[13];
    const float* ff2_w = (const float*)d_in[14];
    const float* ff2_b = (const float*)d_in[15];
    const float* lnf_g = (const float*)d_in[16];
    const float* lnf_b = (const float*)d_in[17];
    float* out = (float*)d_out;

    float *h;
    __half *z, *qkv, *att, *ffn, *wc, *xr;
    cudaGetSymbolAddress((void**)&h,   g_h);
    cudaGetSymbolAddress((void**)&z,   g_z);
    cudaGetSymbolAddress((void**)&qkv, g_qkv);
    cudaGetSymbolAddress((void**)&att, g_att);
    cudaGetSymbolAddress((void**)&ffn, g_ffn);
    cudaGetSymbolAddress((void**)&wc,  g_wc);
    cudaGetSymbolAddress((void**)&xr,  g_xr);

    cudaFuncSetAttribute(attn_h, cudaFuncAttributeMaxDynamicSharedMemorySize,
                         ATT_SMEM_BYTES);

    prep_cvt<<<(TOT / 4 + 255) / 256, 256>>>(w_in, w_out, qkv_w, out_w, ff1_w, ff2_w,
                                             x, wc, xr);

    // embed + LN1(layer 0): h = 16*x@w_in^T + PE; z = LN(h)
    launch_gemm_ln<3>(xr, wc + O_WIN, nullptr, nullptr, h, z, ln1_g, ln1_b, H_);

    for (int l = 0; l < 3; l++) {
        launch_gemm<0, true, 128>(z, wc + O_QKV + (size_t)l * 3 * H_ * H_,
                                  qkv_b + l * 3 * H_, nullptr, qkv, M_, 3 * H_, H_);
        attn_h<<<dim3(S_ / BQ, NHEAD_, B_), 256, ATT_SMEM_BYTES>>>(qkv, att);
        launch_gemm_ln<2>(att, wc + O_OUTW + (size_t)l * H_ * H_,
                          out_b + l * H_, h, h, z, ln2_g + l * H_, ln2_b + l * H_, H_);
        launch_gemm<1, true, 128>(z, wc + O_FF1 + (size_t)l * FFN_ * H_,
                                  ff1_b + l * FFN_, nullptr, ffn, M_, FFN_, H_);
        const float* ng = (l < 2) ? (ln1_g + (l + 1) * H_) : lnf_g;
        const float* nb = (l < 2) ? (ln1_b + (l + 1) * H_) : lnf_b;
        launch_gemm_ln<2>(ffn, wc + O_FF2 + (size_t)l * H_ * FFN_,
                          ff2_b + l * H_, h, h, z, ng, nb, FFN_);
    }

    // final projection from z = LN(h, lnf)
    launch_gemm<0, false, 64>(z, wc + O_WOUT, b_out, nullptr, out, M_, H_, H_);
}

// round 16
// speedup vs baseline: 1.0984x; 1.0984x over previous
#include <cuda_runtime.h>
#include <cuda_fp16.h>
#include <cstdint>
#include <cstddef>

#define B_ 4
#define S_ 2048
#define H_ 256
#define NHEAD_ 4
#define DH_ 64
#define FFN_ 1024
#define M_ (B_ * S_)   // 8192

// weight-scratch segment offsets (elements)
#define O_WIN   0
#define O_WOUT  65536
#define O_QKV   131072
#define O_OUTW  720896
#define O_FF1   917504
#define O_FF2   1703936
#define WTOT    2490368
#define XTOT    2097152
#define TOT     (WTOT + XTOT)

// ---------------- scratch (no allocation allowed) ----------------
__device__ float  g_h  [M_ * H_];          // fp32 residual stream
__device__ __half g_z  [M_ * H_];          // LN output (half)
__device__ __half g_qkv[M_ * 3 * H_];
__device__ __half g_att[M_ * H_];
__device__ __half g_ffn[M_ * FFN_];
__device__ __half g_wc [WTOT];             // half weights
__device__ __half g_xr [XTOT];             // half x

__device__ __forceinline__ void cp_async16(uint32_t smem, const void* gmem) {
    asm volatile("cp.async.cg.shared.global [%0], [%1], 16;\n" :: "r"(smem), "l"(gmem));
}
__device__ __forceinline__ void cp_commit() {
    asm volatile("cp.async.commit_group;\n");
}
template<int N>
__device__ __forceinline__ void cp_wait() {
    asm volatile("cp.async.wait_group %0;\n" :: "n"(N));
}

#define MMA_F16(acc, a, b0, b1)                                               \
    asm volatile(                                                             \
        "mma.sync.aligned.m16n8k16.row.col.f32.f16.f16.f32 "                  \
        "{%0,%1,%2,%3}, {%4,%5,%6,%7}, {%8,%9}, {%0,%1,%2,%3};\n"             \
        : "+f"(acc[0]), "+f"(acc[1]), "+f"(acc[2]), "+f"(acc[3])              \
        : "r"(a[0]), "r"(a[1]), "r"(a[2]), "r"(a[3]), "r"(b0), "r"(b1))

__device__ __forceinline__ void ldsm4(uint32_t& r0, uint32_t& r1, uint32_t& r2,
                                      uint32_t& r3, uint32_t addr) {
    asm volatile("ldmatrix.sync.aligned.m8n8.x4.shared.b16 {%0,%1,%2,%3}, [%4];"
                 : "=r"(r0), "=r"(r1), "=r"(r2), "=r"(r3) : "r"(addr));
}

__device__ __forceinline__ uint32_t h2u(__half2 h) { return *(uint32_t*)&h; }
__device__ __forceinline__ uint32_t pack2(float lo, float hi) {
    __half2 h = __halves2half2(__float2half_rn(lo), __float2half_rn(hi));
    return h2u(h);
}
__device__ __forceinline__ uint32_t sptr(const void* p) {
    return (uint32_t)__cvta_generic_to_shared(const_cast<void*>(p));
}

// ---------------- prep: round weights + x to fp16 once per launch ----------------
__global__ void __launch_bounds__(256)
prep_cvt(const float* __restrict__ w_in, const float* __restrict__ w_out,
         const float* __restrict__ qkv_w, const float* __restrict__ out_w,
         const float* __restrict__ ff1_w, const float* __restrict__ ff2_w,
         const float* __restrict__ x, __half* __restrict__ wc, __half* __restrict__ xr)
{
    int i = (blockIdx.x * 256 + threadIdx.x) * 4;
    if (i >= TOT) return;
    const float* s;
    __half* d;
    if (i < O_QKV) {
        s = (i < O_WOUT) ? (w_in + i) : (w_out + (i - O_WOUT));
        d = wc + i;
    } else if (i < O_OUTW) { s = qkv_w + (i - O_QKV);  d = wc + i; }
    else if (i < O_FF1)    { s = out_w + (i - O_OUTW); d = wc + i; }
    else if (i < O_FF2)    { s = ff1_w + (i - O_FF1);  d = wc + i; }
    else if (i < WTOT)     { s = ff2_w + (i - O_FF2);  d = wc + i; }
    else                   { s = x + (i - WTOT);       d = xr + (i - WTOT); }
    float4 v = *(const float4*)s;
    uint2 o;
    o.x = pack2(v.x, v.y);
    o.y = pack2(v.z, v.w);
    *(uint2*)d = o;
}

#define ASTR 40   // halves per smem row (k-tile 32 + pad 8)

// ---------------- FP16 GEMM, TMx128 tile, ldmatrix fragments ----------------
// C[M,N] = A[M,K] @ W[N,K]^T (+epilogue); A, W half; accumulate fp32.
// MODE 0: +bias, 1: +bias+relu, 2: +bias+residual(fp32), 3: 16*v + PE
// OUTH: write half else fp32.
// TM=128: warps 4m x 2n (32x64); TM=64: warps 2m x 4n (32x32).
template<int MODE, bool OUTH, int TM>
__global__ void __launch_bounds__(256)
gemm_h(const __half* __restrict__ A, const __half* __restrict__ W,
       const float* __restrict__ bias, const float* __restrict__ res,
       void* __restrict__ Cv, int M, int N, int K)
{
    constexpr int RM = TM / 32;
    constexpr int WN = 128 / (8 / RM);
    constexpr int NT = WN / 8;
    extern __shared__ __half hs[];
    __half (*As)[TM][ASTR]  = (__half (*)[TM][ASTR])hs;
    __half (*Bs)[128][ASTR] = (__half (*)[128][ASTR])(hs + 2 * TM * ASTR);

    const int tid = threadIdx.x;
    const int lane = tid & 31;
    const int wid = tid >> 5;
    const int bm = blockIdx.y * TM;
    const int bn = blockIdx.x * 128;
    const int warp_m = (wid % RM) * 32;
    const int warp_n = (wid / RM) * WN;
    const int gid = lane >> 2;
    const int tig = lane & 3;

    // ldmatrix lane-address components
    const int a_row = lane & 15;            // row within 16-row A block
    const int a_kof = (lane >> 4) * 8;      // k offset 0/8
    const int b_row = (lane & 7) + ((lane >> 4) << 3);  // row within 16-row B block
    const int b_kof = ((lane >> 3) & 1) * 8;

    float acc[2][NT][4];
#pragma unroll
    for (int i = 0; i < 2; i++)
#pragma unroll
        for (int j = 0; j < NT; j++)
#pragma unroll
            for (int c = 0; c < 4; c++) acc[i][j][c] = 0.f;

    const int nk = K >> 5;

    auto stage = [&](int buf, int k0) {
#pragma unroll
        for (int p = 0; p < TM / 64; p++) {
            int e = tid + p * 256;
            int r = e >> 2, c = e & 3;
            cp_async16(sptr(&As[buf][r][c * 8]), A + (size_t)(bm + r) * K + k0 + c * 8);
        }
#pragma unroll
        for (int p = 0; p < 2; p++) {
            int e = tid + p * 256;
            int r = e >> 2, c = e & 3;
            cp_async16(sptr(&Bs[buf][r][c * 8]), W + (size_t)(bn + r) * K + k0 + c * 8);
        }
        cp_commit();
    };

    stage(0, 0);

    for (int it = 0; it < nk; it++) {
        if (it + 1 < nk) {
            stage((it + 1) & 1, (it + 1) * 32);
            cp_wait<1>();
        } else {
            cp_wait<0>();
        }
        __syncthreads();

        const __half (*Asb)[ASTR] = As[it & 1];
        const __half (*Bsb)[ASTR] = Bs[it & 1];

#pragma unroll
        for (int ks = 0; ks < 32; ks += 16) {
            uint32_t a[2][4];
#pragma unroll
            for (int mt = 0; mt < 2; mt++) {
                uint32_t ad = sptr(&Asb[warp_m + mt * 16 + a_row][ks + a_kof]);
                ldsm4(a[mt][0], a[mt][1], a[mt][2], a[mt][3], ad);
            }
            uint32_t b[NT][2];
#pragma unroll
            for (int np = 0; np < NT; np += 2) {
                uint32_t bd = sptr(&Bsb[warp_n + np * 8 + b_row][ks + b_kof]);
                ldsm4(b[np][0], b[np][1], b[np + 1][0], b[np + 1][1], bd);
            }
#pragma unroll
            for (int nt = 0; nt < NT; nt++)
#pragma unroll
                for (int mt = 0; mt < 2; mt++)
                    MMA_F16(acc[mt][nt], a[mt], b[nt][0], b[nt][1]);
        }
        __syncthreads();
    }

#pragma unroll
    for (int mt = 0; mt < 2; mt++) {
#pragma unroll
        for (int half_ = 0; half_ < 2; half_++) {
            int m = bm + warp_m + mt * 16 + gid + half_ * 8;
#pragma unroll
            for (int nt = 0; nt < NT; nt++) {
                int n = bn + warp_n + nt * 8 + 2 * tig;
                float v0 = acc[mt][nt][half_ * 2 + 0];
                float v1 = acc[mt][nt][half_ * 2 + 1];
                if (MODE == 3) {
                    int s = m & (S_ - 1);
                    float f0 = expf((float)(n & ~1) * (-9.210340371976184f / 256.0f));
                    float ang = (float)s * f0;
                    v0 = 16.f * v0 + sinf(ang);
                    v1 = 16.f * v1 + cosf(ang);
                } else {
                    v0 += bias[n];
                    v1 += bias[n + 1];
                    if (MODE == 1) { v0 = fmaxf(v0, 0.f); v1 = fmaxf(v1, 0.f); }
                    if (MODE == 2) {
                        const float* rp = res + (size_t)m * N + n;
                        v0 += rp[0];
                        v1 += rp[1];
                    }
                }
                if (OUTH) {
                    *(uint32_t*)((__half*)Cv + (size_t)m * N + n) = pack2(v0, v1);
                } else {
                    *(float2*)((float*)Cv + (size_t)m * N + n) = make_float2(v0, v1);
                }
            }
        }
    }
}

// ---------------- LayerNorm: warp per row, fp32 in, half out ----------------
__global__ void __launch_bounds__(256)
ln_kernel(const float* __restrict__ x, const float* __restrict__ g,
          const float* __restrict__ b, __half* __restrict__ y)
{
    int warp = threadIdx.x >> 5;
    int lane = threadIdx.x & 31;
    int row = blockIdx.x * 8 + warp;
    const float4* xr = (const float4*)(x + (size_t)row * 256);
    float4 v0 = xr[lane], v1 = xr[lane + 32];
    float s = v0.x + v0.y + v0.z + v0.w + v1.x + v1.y + v1.z + v1.w;
#pragma unroll
    for (int o = 16; o; o >>= 1) s += __shfl_xor_sync(~0u, s, o);
    float mu = s * (1.f / 256.f);
    float sq = 0.f;
    sq += (v0.x - mu) * (v0.x - mu) + (v0.y - mu) * (v0.y - mu)
        + (v0.z - mu) * (v0.z - mu) + (v0.w - mu) * (v0.w - mu);
    sq += (v1.x - mu) * (v1.x - mu) + (v1.y - mu) * (v1.y - mu)
        + (v1.z - mu) * (v1.z - mu) + (v1.w - mu) * (v1.w - mu);
#pragma unroll
    for (int o = 16; o; o >>= 1) sq += __shfl_xor_sync(~0u, sq, o);
    float rs = rsqrtf(sq * (1.f / 256.f) + 1e-5f);
    float4 g0 = ((const float4*)g)[lane], g1 = ((const float4*)g)[lane + 32];
    float4 b0 = ((const float4*)b)[lane], b1 = ((const float4*)b)[lane + 32];
    uint2 o0, o1;
    o0.x = pack2((v0.x - mu) * rs * g0.x + b0.x, (v0.y - mu) * rs * g0.y + b0.y);
    o0.y = pack2((v0.z - mu) * rs * g0.z + b0.z, (v0.w - mu) * rs * g0.w + b0.w);
    o1.x = pack2((v1.x - mu) * rs * g1.x + b1.x, (v1.y - mu) * rs * g1.y + b1.y);
    o1.y = pack2((v1.z - mu) * rs * g1.z + b1.z, (v1.w - mu) * rs * g1.w + b1.w);
    uint2* yr = (uint2*)(y + (size_t)row * 256);
    yr[lane] = o0;
    yr[lane + 32] = o1;
}

// ---------------- FP16 tensor-core banded attention (ldmatrix fragments) ----------------
#define BQ 64
#define QSTRH 72
#define KSTRH 72
#define PSTRF 132
#define VSTRH 136
#define PHSTR 136
#define PS_F   (64 * PSTRF)
#define ATT_SMEM_BYTES (PS_F * 4 + 128 * KSTRH * 2 + 64 * VSTRH * 2 + 64 * PHSTR * 2 + 64 * 4)

__global__ void __launch_bounds__(256)
attn_h(const __half* __restrict__ qkv, __half* __restrict__ out)
{
    extern __shared__ float asmem[];
    float*  Ps   = asmem;
    __half* Qs   = (__half*)asmem;
    __half* Ks   = (__half*)(asmem + PS_F);
    __half* Vt   = Ks + 128 * KSTRH;
    __half* Ph   = Vt + 64 * VSTRH;
    float*  Rinv = (float*)(Ph + 64 * PHSTR);

    const int q0 = blockIdx.x * BQ;
    const int h = blockIdx.y;
    const int bb = blockIdx.z;
    const int tid = threadIdx.x;
    const int lane = tid & 31;
    const int wid = tid >> 5;
    const int gid = lane >> 2;
    const int tig = lane & 3;
    const __half* base = qkv + (size_t)bb * S_ * (3 * H_) + h * 64;
    const int kb = q0 - 32;

    const int a_row = lane & 15;
    const int a_kof = (lane >> 4) * 8;
    const int b_row = (lane & 7) + ((lane >> 4) << 3);
    const int b_kof = ((lane >> 3) & 1) * 8;

#pragma unroll
    for (int p = 0; p < 2; p++) {
        int e = tid + p * 256;
        int r = e >> 3, c = e & 7;
        *(uint4*)&Qs[r * QSTRH + c * 8] =
            *(const uint4*)(base + (size_t)(q0 + r) * (3 * H_) + c * 8);
    }
#pragma unroll
    for (int p = 0; p < 4; p++) {
        int e = tid + p * 256;
        int r = e >> 3, c = e & 7;
        int j = kb + r;
        uint4 kk = make_uint4(0, 0, 0, 0);
        if (j >= 0 && j < S_)
            kk = *(const uint4*)(base + (size_t)j * (3 * H_) + H_ + c * 8);
        *(uint4*)&Ks[r * KSTRH + c * 8] = kk;
    }
#pragma unroll
    for (int p = 0; p < 16; p++) {
        int e = tid + p * 256;
        int r = e >> 5;
        int d2 = e & 31;
        int j = kb + r;
        __half2 vv = __halves2half2(__ushort_as_half(0), __ushort_as_half(0));
        if (j >= 0 && j < S_)
            vv = *(const __half2*)(base + (size_t)j * (3 * H_) + 2 * H_ + 2 * d2);
        Vt[(2 * d2) * VSTRH + r]     = __low2half(vv);
        Vt[(2 * d2 + 1) * VSTRH + r] = __high2half(vv);
    }
    __syncthreads();

    const int warp_m = (wid & 3) * 16;

    // ---- Pass 1: raw scores 64x128 (warp tile 16x64) ----
    float sacc[8][4];
    {
        const int warp_n = (wid >> 2) * 64;
#pragma unroll
        for (int j = 0; j < 8; j++)
#pragma unroll
            for (int c = 0; c < 4; c++) sacc[j][c] = 0.f;

#pragma unroll
        for (int ks = 0; ks < 64; ks += 16) {
            uint32_t a[4];
            ldsm4(a[0], a[1], a[2], a[3],
                  sptr(&Qs[(warp_m + a_row) * QSTRH + ks + a_kof]));
            uint32_t b[8][2];
#pragma unroll
            for (int np = 0; np < 8; np += 2) {
                ldsm4(b[np][0], b[np][1], b[np + 1][0], b[np + 1][1],
                      sptr(&Ks[(warp_n + np * 8 + b_row) * KSTRH + ks + b_kof]));
            }
#pragma unroll
            for (int nt = 0; nt < 8; nt++)
                MMA_F16(sacc[nt], a, b[nt][0], b[nt][1]);
        }
    }
    __syncthreads();   // Q reads complete before Ps overwrites the union

    {
        const int warp_n = (wid >> 2) * 64;
#pragma unroll
        for (int nt = 0; nt < 8; nt++) {
#pragma unroll
            for (int half_ = 0; half_ < 2; half_++) {
                int r = warp_m + gid + half_ * 8;
                int c = warp_n + nt * 8 + 2 * tig;
                *(float2*)&Ps[r * PSTRF + c] =
                    make_float2(sacc[nt][half_ * 2] * 0.125f,
                                sacc[nt][half_ * 2 + 1] * 0.125f);
            }
        }
    }
    __syncthreads();

    // ---- Softmax: warp per row, mask in-register, write half P ----
    {
#pragma unroll
        for (int i = 0; i < 8; i++) {
            int r = wid * 8 + i;
            float4 v = *(float4*)&Ps[r * PSTRF + lane * 4];
            float pv[4] = {v.x, v.y, v.z, v.w};
            bool ok[4];
            float mx = -1e30f;
#pragma unroll
            for (int t = 0; t < 4; t++) {
                int c = lane * 4 + t;
                int j = kb + c;
                ok[t] = (c >= r) && (c <= r + 64) && (j >= 0) && (j < S_);
                if (ok[t]) mx = fmaxf(mx, pv[t]);
            }
#pragma unroll
            for (int o = 16; o; o >>= 1) mx = fmaxf(mx, __shfl_xor_sync(~0u, mx, o));
            float s = 0.f;
#pragma unroll
            for (int t = 0; t < 4; t++) {
                pv[t] = ok[t] ? __expf(pv[t] - mx) : 0.f;
                s += pv[t];
            }
#pragma unroll
            for (int o = 16; o; o >>= 1) s += __shfl_xor_sync(~0u, s, o);
            uint2 ph;
            ph.x = pack2(pv[0], pv[1]);
            ph.y = pack2(pv[2], pv[3]);
            *(uint2*)&Ph[r * PHSTR + lane * 4] = ph;
            if (lane == 0) Rinv[r] = 1.f / s;
        }
    }
    __syncthreads();

    // ---- Pass 2: O = P @ V (64x64), warp tile 16x32 ----
    {
        const int warp_n = (wid >> 2) * 32;
        float acc[4][4];
#pragma unroll
        for (int j = 0; j < 4; j++)
#pragma unroll
            for (int c = 0; c < 4; c++) acc[j][c] = 0.f;

#pragma unroll
        for (int k0 = 0; k0 < 128; k0 += 16) {
            uint32_t a[4];
            ldsm4(a[0], a[1], a[2], a[3],
                  sptr(&Ph[(warp_m + a_row) * PHSTR + k0 + a_kof]));
            uint32_t b[4][2];
#pragma unroll
            for (int np = 0; np < 4; np += 2) {
                ldsm4(b[np][0], b[np][1], b[np + 1][0], b[np + 1][1],
                      sptr(&Vt[(warp_n + np * 8 + b_row) * VSTRH + k0 + b_kof]));
            }
#pragma unroll
            for (int nt = 0; nt < 4; nt++)
                MMA_F16(acc[nt], a, b[nt][0], b[nt][1]);
        }

#pragma unroll
        for (int nt = 0; nt < 4; nt++) {
#pragma unroll
            for (int half_ = 0; half_ < 2; half_++) {
                int r = warp_m + gid + half_ * 8;
                float sc = Rinv[r];
                int c = warp_n + nt * 8 + 2 * tig;
                *(uint32_t*)(out + (size_t)(bb * S_ + q0 + r) * H_ + h * 64 + c) =
                    pack2(acc[nt][half_ * 2] * sc, acc[nt][half_ * 2 + 1] * sc);
            }
        }
    }
}

// ---------------- host orchestration ----------------
template<int MODE, bool OUTH, int TM>
static void launch_gemm(const __half* A, const __half* W, const float* bias,
                        const float* res, void* C, int M, int N, int K)
{
    const int smem = (2 * TM * ASTR + 2 * 128 * ASTR) * 2;
    static bool attr_set = false;
    if (!attr_set) {
        cudaFuncSetAttribute(gemm_h<MODE, OUTH, TM>,
                             cudaFuncAttributeMaxDynamicSharedMemorySize, smem);
        attr_set = true;
    }
    dim3 grid(N / 128, M / TM);
    gemm_h<MODE, OUTH, TM><<<grid, 256, smem>>>(A, W, bias, res, C, M, N, K);
}

extern "C" void kernel_launch(void* const* d_in, const int* in_sizes, int n_in,
                              void* d_out, int out_size)
{
    const float* x     = (const float*)d_in[0];
    const float* w_in  = (const float*)d_in[1];
    const float* w_out = (const float*)d_in[2];
    const float* b_out = (const float*)d_in[3];
    const float* qkv_w = (const float*)d_in[4];
    const float* qkv_b = (const float*)d_in[5];
    const float* out_w = (const float*)d_in[6];
    const float* out_b = (const float*)d_in[7];
    const float* ln1_g = (const float*)d_in[8];
    const float* ln1_b = (const float*)d_in[9];
    const float* ln2_g = (const float*)d_in[10];
    const float* ln2_b = (const float*)d_in[11];
    const float* ff1_w = (const float*)d_in[12];
    const float* ff1_b = (const float*)d_in[13];
    const float* ff2_w = (const float*)d_in[14];
    const float* ff2_b = (const float*)d_in[15];
    const float* lnf_g = (const float*)d_in[16];
    const float* lnf_b = (const float*)d_in[17];
    float* out = (float*)d_out;

    float *h;
    __half *z, *qkv, *att, *ffn, *wc, *xr;
    cudaGetSymbolAddress((void**)&h,   g_h);
    cudaGetSymbolAddress((void**)&z,   g_z);
    cudaGetSymbolAddress((void**)&qkv, g_qkv);
    cudaGetSymbolAddress((void**)&att, g_att);
    cudaGetSymbolAddress((void**)&ffn, g_ffn);
    cudaGetSymbolAddress((void**)&wc,  g_wc);
    cudaGetSymbolAddress((void**)&xr,  g_xr);

    cudaFuncSetAttribute(attn_h, cudaFuncAttributeMaxDynamicSharedMemorySize,
                         ATT_SMEM_BYTES);

    prep_cvt<<<(TOT / 4 + 255) / 256, 256>>>(w_in, w_out, qkv_w, out_w, ff1_w, ff2_w,
                                             x, wc, xr);

    // embed: h = 16 * xr @ w_in^T + PE  (fp32 out)
    launch_gemm<3, false, 64>(xr, wc + O_WIN, nullptr, nullptr, h, M_, H_, H_);

    for (int l = 0; l < 3; l++) {
        ln_kernel<<<M_ / 8, 256>>>(h, ln1_g + l * H_, ln1_b + l * H_, z);
        launch_gemm<0, true, 128>(z, wc + O_QKV + (size_t)l * 3 * H_ * H_,
                                  qkv_b + l * 3 * H_, nullptr, qkv, M_, 3 * H_, H_);
        attn_h<<<dim3(S_ / BQ, NHEAD_, B_), 256, ATT_SMEM_BYTES>>>(qkv, att);
        launch_gemm<2, false, 64>(att, wc + O_OUTW + (size_t)l * H_ * H_,
                                  out_b + l * H_, h, h, M_, H_, H_);
        ln_kernel<<<M_ / 8, 256>>>(h, ln2_g + l * H_, ln2_b + l * H_, z);
        launch_gemm<1, true, 128>(z, wc + O_FF1 + (size_t)l * FFN_ * H_,
                                  ff1_b + l * FFN_, nullptr, ffn, M_, FFN_, H_);
        launch_gemm<2, false, 64>(ffn, wc + O_FF2 + (size_t)l * H_ * FFN_,
                                  ff2_b + l * H_, h, h, M_, H_, FFN_);
    }

    ln_kernel<<<M_ / 8, 256>>>(h, lnf_g, lnf_b, z);
    launch_gemm<0, false, 64>(z, wc + O_WOUT, b_out, nullptr, out, M_, H_, H_);
}